// round 14
// baseline (speedup 1.0000x reference)
#include <cuda_runtime.h>
#include <math.h>
#include <stdint.h>

#define Bn   16
#define Tn   2048
#define Dn   512
#define G4n  2048          // 4*D
#define NBLK 128           // persistent blocks (<=148 SMs -> co-resident)
#define PADK 516           // padded row stride (floats); 2064B, 16B-aligned
#define NTH  512           // threads per recurrence block (16 warps)

typedef unsigned long long ull;

// ---------------- device-global scratch (no runtime allocation) ------------
__device__ float g_xg[(size_t)Bn * Tn * G4n];   // 256 MB: xg for layer 0
__device__ float g_h0[2][Bn * Dn];              // layer-0 h, double buffered [b][d]
__device__ float g_h1[2][Bn * Dn];              // layer-1 h, double buffered
__device__ unsigned int g_round_arrive;         // monotonic round counter
__device__ unsigned int          g_bar_count;   // prologue/epilogue barrier
__device__ volatile unsigned int g_bar_gen;

// ---------------- rare full grid barrier (prologue/epilogue only) ----------
__device__ __forceinline__ void grid_barrier() {
    __syncthreads();
    if (threadIdx.x == 0) {
        unsigned int g = g_bar_gen;
        __threadfence();
        if (atomicAdd(&g_bar_count, 1u) == (unsigned)gridDim.x - 1u) {
            g_bar_count = 0;
            __threadfence();
            g_bar_gen = g + 1;
        } else {
            while (g_bar_gen == g) { }
        }
        __threadfence();
    }
    __syncthreads();
}

// ---------------- round-barrier primitives ----------------------------------
__device__ __forceinline__ void red_release_add(unsigned int* p, unsigned int v) {
    asm volatile("red.release.gpu.global.add.u32 [%0], %1;" :: "l"(p), "r"(v) : "memory");
}
__device__ __forceinline__ unsigned int ld_acquire_u32(const unsigned int* p) {
    unsigned int v;
    asm volatile("ld.acquire.gpu.global.u32 %0, [%1];" : "=r"(v) : "l"(p) : "memory");
    return v;
}

// ---------------- packed fp32x2 helpers (sm_103a FFMA2, PTX-only) ----------
__device__ __forceinline__ void ffma2(ull& d, ull a, ull b) {
    asm("fma.rn.f32x2 %0, %1, %2, %0;" : "+l"(d) : "l"(a), "l"(b));
}
__device__ __forceinline__ ull pack2(float lo, float hi) {
    ull r;
    asm("mov.b64 %0, {%1, %2};" : "=l"(r) : "f"(lo), "f"(hi));
    return r;
}
__device__ __forceinline__ void unpack2(ull v, float& lo, float& hi) {
    asm("mov.b64 {%0, %1}, %2;" : "=f"(lo), "=f"(hi) : "l"(v));
}
__device__ __forceinline__ float fsum2(ull v) {
    float lo, hi; unpack2(v, lo, hi); return lo + hi;
}

__device__ __forceinline__ float fsig(float x) {
    return 1.0f / (1.0f + __expf(-x));
}
__device__ __forceinline__ float ftanh_(float x) {
    return 2.0f / (1.0f + __expf(-2.0f * x)) - 1.0f;
}

// ============================================================================
// SGEMM + bias: C[M=32768, N=2048] = A[M,512] @ W[512,2048] + bias  (layer 0)
// 128x128 tile, 256 threads, 8x8 microtile, BK=8, fp32x2 packed FMA.
// ============================================================================
__global__ void __launch_bounds__(256, 2) gemm_bias_kernel(
    const float* __restrict__ A,
    const float* __restrict__ W,
    const float* __restrict__ bias,
    float* __restrict__ C)
{
    const int K = Dn, N = G4n;
    __shared__ __align__(16) float As[8][132];   // transposed [k][m]
    __shared__ __align__(16) float Bs[8][128];   // [k][n]

    const int tid  = threadIdx.x;
    const int bm   = blockIdx.y << 7;
    const int bn   = blockIdx.x << 7;
    const int arow = tid >> 1, acol = (tid & 1) << 2;
    const int brow = tid >> 5, bcol = (tid & 31) << 2;
    const int tr   = (tid >> 4) << 2;
    const int tc   = (tid & 15) << 2;

    ull acc2[4][8];
#pragma unroll
    for (int p = 0; p < 4; ++p)
#pragma unroll
        for (int j = 0; j < 8; ++j) acc2[p][j] = 0ull;

    float4 areg = *reinterpret_cast<const float4*>(&A[(size_t)(bm + arow) * K + acol]);
    float4 breg = *reinterpret_cast<const float4*>(&W[(size_t)brow * N + bn + bcol]);

#pragma unroll 1
    for (int k0 = 0; k0 < K; k0 += 8) {
        As[acol + 0][arow] = areg.x;
        As[acol + 1][arow] = areg.y;
        As[acol + 2][arow] = areg.z;
        As[acol + 3][arow] = areg.w;
        *reinterpret_cast<float4*>(&Bs[brow][bcol]) = breg;
        __syncthreads();

        if (k0 + 8 < K) {
            areg = *reinterpret_cast<const float4*>(&A[(size_t)(bm + arow) * K + (k0 + 8) + acol]);
            breg = *reinterpret_cast<const float4*>(&W[(size_t)(k0 + 8 + brow) * N + bn + bcol]);
        }

#pragma unroll
        for (int kk = 0; kk < 8; ++kk) {
            float4 a0 = *reinterpret_cast<const float4*>(&As[kk][tr]);
            float4 a1 = *reinterpret_cast<const float4*>(&As[kk][tr + 64]);
            float4 b0 = *reinterpret_cast<const float4*>(&Bs[kk][tc]);
            float4 b1 = *reinterpret_cast<const float4*>(&Bs[kk][tc + 64]);
            ull ap[4] = { pack2(a0.x, a0.y), pack2(a0.z, a0.w),
                          pack2(a1.x, a1.y), pack2(a1.z, a1.w) };
            float bv[8] = {b0.x, b0.y, b0.z, b0.w, b1.x, b1.y, b1.z, b1.w};
#pragma unroll
            for (int j = 0; j < 8; ++j) {
                ull bd = pack2(bv[j], bv[j]);
                ffma2(acc2[0][j], ap[0], bd);
                ffma2(acc2[1][j], ap[1], bd);
                ffma2(acc2[2][j], ap[2], bd);
                ffma2(acc2[3][j], ap[3], bd);
            }
        }
        __syncthreads();
    }

    float4 bi0 = *reinterpret_cast<const float4*>(&bias[bn + tc]);
    float4 bi1 = *reinterpret_cast<const float4*>(&bias[bn + tc + 64]);
    float bvv[8] = {bi0.x, bi0.y, bi0.z, bi0.w, bi1.x, bi1.y, bi1.z, bi1.w};

#pragma unroll
    for (int p = 0; p < 4; ++p) {
        float rlo[8], rhi[8];
#pragma unroll
        for (int j = 0; j < 8; ++j) unpack2(acc2[p][j], rlo[j], rhi[j]);
        int i0   = 2 * p;
        int r_lo = bm + ((i0 < 4) ? (tr + i0) : (64 + tr + i0 - 4));
        int r_hi = r_lo + 1;
        float4 o;
        o = make_float4(rlo[0] + bvv[0], rlo[1] + bvv[1], rlo[2] + bvv[2], rlo[3] + bvv[3]);
        *reinterpret_cast<float4*>(&C[(size_t)r_lo * N + bn + tc]) = o;
        o = make_float4(rlo[4] + bvv[4], rlo[5] + bvv[5], rlo[6] + bvv[6], rlo[7] + bvv[7]);
        *reinterpret_cast<float4*>(&C[(size_t)r_lo * N + bn + tc + 64]) = o;
        o = make_float4(rhi[0] + bvv[0], rhi[1] + bvv[1], rhi[2] + bvv[2], rhi[3] + bvv[3]);
        *reinterpret_cast<float4*>(&C[(size_t)r_hi * N + bn + tc]) = o;
        o = make_float4(rhi[4] + bvv[4], rhi[5] + bvv[5], rhi[6] + bvv[6], rhi[7] + bvv[7]);
        *reinterpret_cast<float4*>(&C[(size_t)r_hi * N + bn + tc + 64]) = o;
    }
}

// ============================================================================
// Fused two-layer wavefront LSTM. 128 blocks x 512 threads (16 warps).
// Round r (0..Tn): layer-0 computes t=r (r<Tn), layer-1 computes t=r-1 (r>=1).
// Block bk owns h-cols d=4bk+m (m=0..3) for BOTH layers => 16 gate cols/layer.
// Layer-1 gate = h0(t) @ Wx1 + h1(t-1) @ Wh1 + b1 (no separate GEMM).
// Warp decomposition: warp = kh(4) x chi(2) x b1h(2); lane = clo(8) x b1q(4).
// Each thread: k-quarter (128 floats), col cc, batches b1/b1+8.
// Sync: one red.release arrival per block; tid0-only acquire poll.
// ============================================================================
__global__ void __launch_bounds__(NTH, 1) lstm_fused_kernel(
    const float* __restrict__ Wh0,
    const float* __restrict__ Wx1,
    const float* __restrict__ Wh1,
    const float* __restrict__ bias1,   // [2048] layer-1 bias
    const float* __restrict__ xg0,     // g_xg (layer-0 input gates, bias added)
    const float* __restrict__ x,       // residual input [16,2048,512]
    float* __restrict__ out)           // [16,2048,512]
{
    extern __shared__ float sm[];
    float* W0  = sm;                   // [16][PADK]
    float* W1x = sm + 16 * PADK;       // [16][PADK]
    float* W1h = sm + 32 * PADK;       // [16][PADK]
    float* H0  = sm + 48 * PADK;       // [16][PADK]
    float* H1  = sm + 64 * PADK;       // [16][PADK]
    float* psum = sm + 80 * PADK;      // [3][4][16][16] = 3072
    float* gbuf = psum + 3072;         // [2][16][16]    = 512
    float* cbuf = gbuf + 512;          // [128] c-state: [L][b][m]
    float* b1s  = cbuf + 128;          // [16] layer-1 bias slice

    const int tid = threadIdx.x;
    const int bk  = blockIdx.x;

    // ---- prologue: W slices -> SMEM, bias, zero c / h buffers -------------
    for (int idx = tid; idx < 3 * 16 * Dn; idx += NTH) {
        int s = idx >> 13;                 // 8192 per slice
        int rm = idx & 8191;
        int c = rm >> 9, k = rm & 511;
        int gcol = ((c >> 2) << 9) + (bk << 2) + (c & 3);
        const float* src = (s == 0) ? Wh0 : ((s == 1) ? Wx1 : Wh1);
        sm[s * 16 * PADK + c * PADK + k] = src[(size_t)k * G4n + gcol];
    }
    if (tid < 16)
        b1s[tid] = bias1[((tid >> 2) << 9) + (bk << 2) + (tid & 3)];
    if (tid < 128) cbuf[tid] = 0.0f;
    if (tid < 256) {   // zero both parities of both h buffers for owned columns
        int par = tid >> 7, L = (tid >> 6) & 1, s = tid & 63;
        int b = s >> 2, m = s & 3, d = (bk << 2) + m;
        float* dst = L ? g_h1[par] : g_h0[par];
        dst[b * Dn + d] = 0.0f;
    }
    __threadfence();
    grid_barrier();

    // ---- compute-phase ids -------------------------------------------------
    const int lane = tid & 31, warp = tid >> 5;
    const int clo = lane & 7,  b1q = lane >> 3;
    const int kh  = warp >> 2;                 // 0..3: k-quarter
    const int chi = (warp >> 1) & 1, b1h = warp & 1;
    const int cc  = clo + (chi << 3);          // 0..15
    const int b1  = b1q + (b1h << 2);          // 0..7
    const int b2  = b1 + 8;
    const ulonglong2* W0p  = reinterpret_cast<const ulonglong2*>(W0  + cc * PADK + kh * 128);
    const ulonglong2* W1xp = reinterpret_cast<const ulonglong2*>(W1x + cc * PADK + kh * 128);
    const ulonglong2* W1hp = reinterpret_cast<const ulonglong2*>(W1h + cc * PADK + kh * 128);
    const ulonglong2* H0a  = reinterpret_cast<const ulonglong2*>(H0 + b1 * PADK + kh * 128);
    const ulonglong2* H0b  = reinterpret_cast<const ulonglong2*>(H0 + b2 * PADK + kh * 128);
    const ulonglong2* H1a  = reinterpret_cast<const ulonglong2*>(H1 + b1 * PADK + kh * 128);
    const ulonglong2* H1b  = reinterpret_cast<const ulonglong2*>(H1 + b2 * PADK + kh * 128);

    // reduce-phase ids: one (L, b, c) gate unit per thread
    const int rL = tid >> 8;                   // 0..1
    const int ro = tid & 255;                  // b*16 + c
    const int fb = ro >> 4, fc = ro & 15;
    const int fgc = ((fc >> 2) << 9) + (bk << 2) + (fc & 3);
    // gate-phase ids (tid < 128): L, b, m
    const int gL = tid >> 6, gs = tid & 63;
    const int gb = gs >> 2, gm = gs & 3;
    const int gd = (bk << 2) + gm;

#pragma unroll 1
    for (int r = 0; r <= Tn; ++r) {
        // 0. wait for round-r inputs (published at end of round r-1)
        if (r > 0) {
            if (tid == 0) {
                unsigned int target = 128u * (unsigned)r;
                while (ld_acquire_u32(&g_round_arrive) < target) { }
            }
            __syncthreads();
        }

        // 1. broadcast copies: h0(r-1), h1(r-2) -> SMEM
        const float4* s0 = reinterpret_cast<const float4*>(g_h0[(r + 1) & 1]);
        const float4* s1 = reinterpret_cast<const float4*>(g_h1[(r + 1) & 1]);
#pragma unroll
        for (int j = 0; j < 4; ++j) {
            int idx = j * NTH + tid;            // 0..2047 float4
            int b = idx >> 7, k4 = idx & 127;
            float4 v0 = __ldcg(s0 + idx);
            float4 v1 = __ldcg(s1 + idx);
            *reinterpret_cast<float4*>(H0 + b * PADK + (k4 << 2)) = v0;
            *reinterpret_cast<float4*>(H1 + b * PADK + (k4 << 2)) = v1;
        }
        // 2. prefetches: xg0 (layer-0 reduce threads), x residual (gate threads)
        float xv = 0.0f;
        if (rL == 0 && r < Tn)
            xv = __ldg(&xg0[((size_t)fb * Tn + r) * G4n + fgc]);
        float xrv = 0.0f;
        if (tid < 128 && gL == 1 && r >= 1)
            xrv = __ldg(&x[((size_t)gb * Tn + (r - 1)) * Dn + gd]);

        __syncthreads();   // H0/H1 ready

        // 3a. fused segments 0+1: (Wh0, Wx1) x h0, two batches each
        ull a00 = 0, a01 = 0, a10 = 0, a11 = 0;   // seg0: b1, b2
        ull s00 = 0, s01 = 0, s10 = 0, s11 = 0;   // seg1: b1, b2
#pragma unroll 8
        for (int i = 0; i < 32; ++i) {            // 32 x 16B = 128 floats
            ulonglong2 w0 = W0p[i];
            ulonglong2 w1 = W1xp[i];
            ulonglong2 ha = H0a[i];
            ulonglong2 hb = H0b[i];
            ffma2(a00, w0.x, ha.x); ffma2(a01, w0.y, ha.y);
            ffma2(a10, w0.x, hb.x); ffma2(a11, w0.y, hb.y);
            ffma2(s00, w1.x, ha.x); ffma2(s01, w1.y, ha.y);
            ffma2(s10, w1.x, hb.x); ffma2(s11, w1.y, hb.y);
        }
        // 3b. segment 2: Wh1 x h1
        ull t00 = 0, t01 = 0, t10 = 0, t11 = 0;
#pragma unroll 8
        for (int i = 0; i < 32; ++i) {
            ulonglong2 w  = W1hp[i];
            ulonglong2 ha = H1a[i];
            ulonglong2 hb = H1b[i];
            ffma2(t00, w.x, ha.x); ffma2(t01, w.y, ha.y);
            ffma2(t10, w.x, hb.x); ffma2(t11, w.y, hb.y);
        }
        // psum[seg][kh][b][c]
        psum[((0 * 4 + kh) * 16 + b1) * 16 + cc] = fsum2(a00) + fsum2(a01);
        psum[((0 * 4 + kh) * 16 + b2) * 16 + cc] = fsum2(a10) + fsum2(a11);
        psum[((1 * 4 + kh) * 16 + b1) * 16 + cc] = fsum2(s00) + fsum2(s01);
        psum[((1 * 4 + kh) * 16 + b2) * 16 + cc] = fsum2(s10) + fsum2(s11);
        psum[((2 * 4 + kh) * 16 + b1) * 16 + cc] = fsum2(t00) + fsum2(t01);
        psum[((2 * 4 + kh) * 16 + b2) * 16 + cc] = fsum2(t10) + fsum2(t11);
        __syncthreads();

        // 4. reduce k-quarters -> gate pre-activations (one unit per thread)
        {
            float v;
            if (rL == 0) {
                v = xv + (psum[0 * 256 + ro] + psum[1 * 256 + ro])
                       + (psum[2 * 256 + ro] + psum[3 * 256 + ro]);
            } else {
                v = b1s[fc]
                  + (psum[4 * 256 + ro] + psum[5 * 256 + ro])
                  + (psum[6 * 256 + ro] + psum[7 * 256 + ro])
                  + (psum[8 * 256 + ro] + psum[9 * 256 + ro])
                  + (psum[10 * 256 + ro] + psum[11 * 256 + ro]);
            }
            gbuf[tid & 511] = v;   // tid = L*256 + ro  (layout [L][b][c])
        }
        __syncthreads();

        // 5. gate phase: 128 threads, one (L,b,m) each
        if (tid < 128) {
            bool active = (gL == 0) ? (r < Tn) : (r >= 1);
            if (active) {
                const float* gp = gbuf + gL * 256 + gb * 16;
                float gi = gp[0  + gm];
                float gf = gp[4  + gm];
                float gg = gp[8  + gm];
                float go = gp[12 + gm];
                float cn = fsig(gf) * cbuf[tid] + fsig(gi) * ftanh_(gg);
                float h  = fsig(go) * ftanh_(cn);
                cbuf[tid] = cn;
                float* dst = gL ? g_h1[r & 1] : g_h0[r & 1];
                __stcg(&dst[gb * Dn + gd], h);
                if (gL == 1)
                    out[((size_t)gb * Tn + (r - 1)) * Dn + gd] = h + xrv;
            }
        }
        __syncthreads();   // order h stores (CTA scope) before release arrival
        if (tid == 0) red_release_add(&g_round_arrive, 1u);
    }

    // ---- epilogue: drain, then reset the round counter for the next launch
    grid_barrier();
    if (bk == 0 && tid == 0) g_round_arrive = 0u;
}

// ============================================================================
extern "C" void kernel_launch(void* const* d_in, const int* in_sizes, int n_in,
                              void* d_out, int out_size) {
    const float* x  = (const float*)d_in[0];   // [16,2048,512]
    const float* Wx = (const float*)d_in[1];   // [2,512,2048]
    const float* Wh = (const float*)d_in[2];   // [2,512,2048]
    const float* bb = (const float*)d_in[3];   // [2,2048]
    float* out = (float*)d_out;                // [16,2048,512]

    float* xg_p;
    cudaGetSymbolAddress((void**)&xg_p, g_xg);

    const int smem = (80 * PADK + 3072 + 512 + 128 + 16) * (int)sizeof(float); // ~180 KB
    cudaFuncSetAttribute(lstm_fused_kernel,
                         cudaFuncAttributeMaxDynamicSharedMemorySize, smem);

    dim3 ggrid(G4n / 128, (Bn * Tn) / 128);    // 16 x 256

    // layer-0 input GEMM (bias0 folded in)
    gemm_bias_kernel<<<ggrid, 256>>>(x, Wx, bb, xg_p);

    // fused two-layer wavefront recurrence (+ residual)
    lstm_fused_kernel<<<NBLK, NTH, smem>>>(
        Wh,                        // Wh0
        Wx + (size_t)Dn * G4n,     // Wx1
        Wh + (size_t)Dn * G4n,     // Wh1
        bb + G4n,                  // bias1
        xg_p, x, out);
}